// round 11
// baseline (speedup 1.0000x reference)
#include <cuda_runtime.h>
#include <cuda_fp16.h>
#include <math.h>
#include <stdint.h>

// ---------------- problem constants ----------------
#define Bz 32
#define TE 2048
#define TDd 64
#define Dd 1024
#define Mrows (Bz * TE)      // 65536

// ---------------- scratch (device globals) ----------------
__device__ __half g_A1[(size_t)Mrows * Dd];   // fp16(enc)
__device__ __half g_B1[(size_t)Dd * Dd];      // W^T fp16 : [n][k]
__device__ float g_dU[Bz * Dd];
__device__ float g_scores[Bz * TE];
__device__ float g_weights[Bz * TE];

// ---------------- helpers ----------------
__device__ __forceinline__ uint32_t smem_to_u32(const void* p) {
    uint32_t a;
    asm("{ .reg .u64 t; cvta.to.shared.u64 t, %1; cvt.u32.u64 %0, t; }" : "=r"(a) : "l"(p));
    return a;
}
__device__ __forceinline__ void cp16(uint32_t s, const void* g) {
    asm volatile("cp.async.cg.shared.global [%0], [%1], 16;" :: "r"(s), "l"(g));
}
#define CP_COMMIT() asm volatile("cp.async.commit_group;" ::: "memory")
#define CP_WAIT(n)  asm volatile("cp.async.wait_group %0;" :: "n"(n) : "memory")
#define LDSM_X4(r0, r1, r2, r3, addr) \
    asm volatile("ldmatrix.sync.aligned.m8n8.x4.shared.b16 {%0,%1,%2,%3}, [%4];" \
        : "=r"(r0), "=r"(r1), "=r"(r2), "=r"(r3) : "r"(addr))
#define MMA16816F(d0, d1, d2, d3, a0, a1, a2, a3, b0, b1) \
    asm volatile("mma.sync.aligned.m16n8k16.row.col.f32.f16.f16.f32 " \
        "{%0,%1,%2,%3}, {%4,%5,%6,%7}, {%8,%9}, {%0,%1,%2,%3};" \
        : "+f"(d0), "+f"(d1), "+f"(d2), "+f"(d3) \
        : "r"(a0), "r"(a1), "r"(a2), "r"(a3), "r"(b0), "r"(b1))

__device__ __forceinline__ uint32_t sw128(uint32_t off) {
    return off ^ ((off >> 3) & 0x70);
}
__device__ __forceinline__ float fast_tanh(float x) {
    float ax = fabsf(x);
    float e  = __expf(2.0f * ax);
    float t  = 1.0f - __fdividef(2.0f, e + 1.0f);
    return copysignf(t, x);
}

// ---------------- GEMM tiling ----------------
#define BM 128
#define BN 256
#define BKE 64                      // fp16 k per chunk (128 B rows)
#define NKC1 16                     // 16 k-chunks
#define A_BYTES 16384               // 128 rows * 128 B
#define B_BYTES 32768               // 256 rows * 128 B
#define STG_B (A_BYTES + B_BYTES)   // 49152
#define SMEM_TOTAL (3 * STG_B)      // 147456

// ---------------- setup kernels ----------------
__global__ void convert_A_kernel(const float* __restrict__ enc) {
    size_t i = ((size_t)blockIdx.x * blockDim.x + threadIdx.x) * 8;
    float4 v0 = *(const float4*)(enc + i);
    float4 v1 = *(const float4*)(enc + i + 4);
    __half2 h[4];
    h[0] = __floats2half2_rn(v0.x, v0.y);
    h[1] = __floats2half2_rn(v0.z, v0.w);
    h[2] = __floats2half2_rn(v1.x, v1.y);
    h[3] = __floats2half2_rn(v1.z, v1.w);
    *(uint4*)(g_A1 + i) = *(uint4*)h;
}

__global__ void convert_W_kernel(const float* __restrict__ W) {
    int id = blockIdx.x * 256 + threadIdx.x;
    int n = id >> 10, k = id & 1023;
    g_B1[(size_t)n * Dd + k] = __float2half(W[(size_t)k * Dd + n]);
    if (id < Bz * TE) g_scores[id] = 0.0f;
    if (id < Bz * Dd) g_dU[id] = 0.0f;
}

// dU[b][f] = sum_k dec_last[b][k] * U[k][f]  ; grid (4, 32)
__global__ void dU_kernel(const float* __restrict__ dec, const float* __restrict__ U) {
    const int f  = blockIdx.x * 256 + threadIdx.x;
    const int k0 = blockIdx.y * 32;
    __shared__ float sdec[Bz][32];
#pragma unroll
    for (int j = 0; j < 4; j++) {
        int idx = threadIdx.x + j * 256;
        int b = idx >> 5, kk = idx & 31;
        sdec[b][kk] = dec[((size_t)b * TDd + (TDd - 1)) * Dd + k0 + kk];
    }
    __syncthreads();
    float acc[Bz];
#pragma unroll
    for (int b = 0; b < Bz; b++) acc[b] = 0.0f;
#pragma unroll
    for (int kk = 0; kk < 32; kk++) {
        float u = U[(size_t)(k0 + kk) * Dd + f];
#pragma unroll
        for (int b = 0; b < Bz; b++) acc[b] = fmaf(u, sdec[b][kk], acc[b]);
    }
#pragma unroll
    for (int b = 0; b < Bz; b++) atomicAdd(&g_dU[b * Dd + f], acc[b]);
}

// ---------------- fused GEMM + epilogue ----------------
// stage layout: A at +0 (128 rows), B at +A_BYTES (256 rows)
__device__ __forceinline__ void load_chunk(uint32_t sbase, int stage, int c,
                                           int mbase, int nbase, int tid) {
    const int kb = c * BKE;
    uint32_t sA = sbase + stage * STG_B;
    uint32_t sB = sA + A_BYTES;
#pragma unroll
    for (int i = 0; i < 4; i++) {                   // A: 1024 cp16
        int u = tid + i * 256;
        int r = u >> 3, ch = u & 7;
        uint32_t off = sw128((uint32_t)(r * 128 + ch * 16));
        cp16(sA + off, g_A1 + (size_t)(mbase + r) * Dd + kb + ch * 8);
    }
#pragma unroll
    for (int i = 0; i < 8; i++) {                   // B: 2048 cp16
        int u = tid + i * 256;
        int r = u >> 3, ch = u & 7;
        uint32_t off = sw128((uint32_t)(r * 128 + ch * 16));
        cp16(sB + off, g_B1 + (size_t)(nbase + r) * Dd + kb + ch * 8);
    }
    CP_COMMIT();
}

__global__ void __launch_bounds__(256, 1) gemm_score_mma(const float* __restrict__ V) {
    extern __shared__ char smem[];
    uint32_t sbase = smem_to_u32(smem);

    const int tid  = threadIdx.x;
    const int wid  = tid >> 5;
    const int lane = tid & 31;
    const int wm   = wid >> 2;      // 0..1 : 64 rows
    const int wn   = wid & 3;       // 0..3 : 64 cols

    const int nblk  = blockIdx.x & 3;
    const int mblk  = blockIdx.x >> 2;
    const int mbase = mblk * BM;
    const int nbase = nblk * BN;
    const int b     = mbase >> 11;

    float acc[4][8][4];
#pragma unroll
    for (int mt = 0; mt < 4; mt++)
#pragma unroll
        for (int nt = 0; nt < 8; nt++)
#pragma unroll
            for (int i = 0; i < 4; i++) acc[mt][nt][i] = 0.0f;

    const int a_r  = lane & 15;
    const int a_kc = lane >> 4;
    const int b_n  = ((lane >> 4) & 1) * 8 + (lane & 7);
    const int b_kc = (lane >> 3) & 1;

    load_chunk(sbase, 0, 0, mbase, nbase, tid);
    load_chunk(sbase, 1, 1, mbase, nbase, tid);

    int stage = 0;
    for (int c = 0; c < NKC1; c++) {
        if (c + 2 < NKC1) { CP_WAIT(1); } else { CP_WAIT(0); }
        __syncthreads();
        if (c + 2 < NKC1) {
            int ns = stage + 2; if (ns >= 3) ns -= 3;
            load_chunk(sbase, ns, c + 2, mbase, nbase, tid);
        }

        const uint32_t sA = sbase + stage * STG_B;
        const uint32_t sB = sA + A_BYTES;
#pragma unroll
        for (int ks = 0; ks < 4; ks++) {
            uint32_t af[4][4], bf[4][4];
#pragma unroll
            for (int mt = 0; mt < 4; mt++) {
                int row = wm * 64 + mt * 16 + a_r;
                uint32_t off = sw128((uint32_t)(row * 128 + (ks * 2 + a_kc) * 16));
                LDSM_X4(af[mt][0], af[mt][1], af[mt][2], af[mt][3], sA + off);
            }
#pragma unroll
            for (int p = 0; p < 4; p++) {
                int row = wn * 64 + p * 16 + b_n;
                uint32_t off = sw128((uint32_t)(row * 128 + (ks * 2 + b_kc) * 16));
                LDSM_X4(bf[p][0], bf[p][1], bf[p][2], bf[p][3], sB + off);
            }
#pragma unroll
            for (int mt = 0; mt < 4; mt++)
#pragma unroll
                for (int nt = 0; nt < 8; nt++)
                    MMA16816F(acc[mt][nt][0], acc[mt][nt][1], acc[mt][nt][2], acc[mt][nt][3],
                              af[mt][0], af[mt][1], af[mt][2], af[mt][3],
                              bf[nt >> 1][(nt & 1) * 2], bf[nt >> 1][(nt & 1) * 2 + 1]);
        }
        stage++; if (stage >= 3) stage = 0;
    }

    // ---- fused epilogue: scores[m] += sum_n V[n]*tanh(C[m][n] + dU[b][n]) ----
    const int q = lane >> 2;
    const int t4 = lane & 3;
#pragma unroll
    for (int mt = 0; mt < 4; mt++) {
        float s0 = 0.0f, s1 = 0.0f;
#pragma unroll
        for (int nt = 0; nt < 8; nt++) {
            int n0 = nbase + wn * 64 + nt * 8 + 2 * t4;
            float v0 = V[n0], v1 = V[n0 + 1];
            float u0 = g_dU[b * Dd + n0], u1 = g_dU[b * Dd + n0 + 1];
            s0 = fmaf(v0, fast_tanh(acc[mt][nt][0] + u0), s0);
            s0 = fmaf(v1, fast_tanh(acc[mt][nt][1] + u1), s0);
            s1 = fmaf(v0, fast_tanh(acc[mt][nt][2] + u0), s1);
            s1 = fmaf(v1, fast_tanh(acc[mt][nt][3] + u1), s1);
        }
        s0 += __shfl_xor_sync(0xFFFFFFFF, s0, 1);
        s0 += __shfl_xor_sync(0xFFFFFFFF, s0, 2);
        s1 += __shfl_xor_sync(0xFFFFFFFF, s1, 1);
        s1 += __shfl_xor_sync(0xFFFFFFFF, s1, 2);
        if (t4 == 0) {
            int row = mbase + wm * 64 + mt * 16 + q;
            atomicAdd(&g_scores[row], s0);
            atomicAdd(&g_scores[row + 8], s1);
        }
    }
}

// ---------------- softmax & context ----------------
__global__ void softmax_kernel(float* __restrict__ out_weights) {
    const int b = blockIdx.x;
    const int tid = threadIdx.x;
    __shared__ float red[256];
    float local[8];
    float mx = -INFINITY;
#pragma unroll
    for (int i = 0; i < 8; i++) {
        local[i] = g_scores[b * TE + tid + i * 256];
        mx = fmaxf(mx, local[i]);
    }
    red[tid] = mx;
    __syncthreads();
    for (int s = 128; s > 0; s >>= 1) {
        if (tid < s) red[tid] = fmaxf(red[tid], red[tid + s]);
        __syncthreads();
    }
    mx = red[0];
    __syncthreads();
    float sum = 0.0f;
#pragma unroll
    for (int i = 0; i < 8; i++) { local[i] = __expf(local[i] - mx); sum += local[i]; }
    red[tid] = sum;
    __syncthreads();
    for (int s = 128; s > 0; s >>= 1) {
        if (tid < s) red[tid] += red[tid + s];
        __syncthreads();
    }
    const float inv = 1.0f / red[0];
#pragma unroll
    for (int i = 0; i < 8; i++) {
        float w = local[i] * inv;
        g_weights[b * TE + tid + i * 256]   = w;
        out_weights[b * TE + tid + i * 256] = w;
    }
}

__global__ void context_kernel(float* __restrict__ out_context) {
    const int b = blockIdx.x;
    const int e = blockIdx.y * 256 + threadIdx.x;
    __shared__ float sw[TE];
    for (int i = threadIdx.x; i < TE; i += 256) sw[i] = g_weights[b * TE + i];
    __syncthreads();
    const __half* base = g_A1 + (size_t)b * TE * Dd + e;
    float acc = 0.0f;
#pragma unroll 8
    for (int t = 0; t < TE; t++)
        acc = fmaf(sw[t], __half2float(base[(size_t)t * Dd]), acc);
    out_context[b * Dd + e] = acc;
}

// ---------------- launch ----------------
extern "C" void kernel_launch(void* const* d_in, const int* in_sizes, int n_in,
                              void* d_out, int out_size) {
    const float* enc = (const float*)d_in[0];
    const float* dec = (const float*)d_in[1];
    const float* W_a = (const float*)d_in[2];
    const float* U_a = (const float*)d_in[3];
    const float* V_a = (const float*)d_in[4];
    float* out = (float*)d_out;
    float* out_context = out;            // 32*1024
    float* out_weights = out + Bz * Dd;  // 32*2048

    static int smem_set = 0;
    if (!smem_set) {
        cudaFuncSetAttribute(gemm_score_mma, cudaFuncAttributeMaxDynamicSharedMemorySize, SMEM_TOTAL);
        smem_set = 1;
    }

    convert_A_kernel<<<(Mrows * (Dd / 8)) / 256, 256>>>(enc);
    convert_W_kernel<<<(Dd * Dd) / 256, 256>>>(W_a);
    {
        dim3 g(Dd / 256, 32);
        dU_kernel<<<g, 256>>>(dec, U_a);
    }
    gemm_score_mma<<<(Mrows / BM) * (Dd / BN), 256, SMEM_TOTAL>>>(V_a);
    softmax_kernel<<<Bz, 256>>>(out_weights);
    {
        dim3 g(Bz, Dd / 256);
        context_kernel<<<g, 256>>>(out_context);
    }
}

// round 12
// speedup vs baseline: 1.4678x; 1.4678x over previous
#include <cuda_runtime.h>
#include <cuda_fp16.h>
#include <math.h>
#include <stdint.h>

// ---------------- problem constants ----------------
#define Bz 32
#define TE 2048
#define TDd 64
#define Dd 1024
#define Mrows (Bz * TE)      // 65536

// ---------------- scratch (device globals) ----------------
__device__ __half g_A1[(size_t)Mrows * Dd];   // fp16(enc)
__device__ __half g_B1[(size_t)Dd * Dd];      // W^T fp16 : [n][k]
__device__ float g_dU[Bz * Dd];
__device__ float g_scores[Bz * TE];
__device__ float g_weights[Bz * TE];

// ---------------- helpers ----------------
__device__ __forceinline__ uint32_t smem_to_u32(const void* p) {
    uint32_t a;
    asm("{ .reg .u64 t; cvta.to.shared.u64 t, %1; cvt.u32.u64 %0, t; }" : "=r"(a) : "l"(p));
    return a;
}
__device__ __forceinline__ void cp16(uint32_t s, const void* g) {
    asm volatile("cp.async.cg.shared.global [%0], [%1], 16;" :: "r"(s), "l"(g));
}
#define CP_COMMIT() asm volatile("cp.async.commit_group;" ::: "memory")
#define CP_WAIT(n)  asm volatile("cp.async.wait_group %0;" :: "n"(n) : "memory")
#define LDSM_X4(r0, r1, r2, r3, addr) \
    asm volatile("ldmatrix.sync.aligned.m8n8.x4.shared.b16 {%0,%1,%2,%3}, [%4];" \
        : "=r"(r0), "=r"(r1), "=r"(r2), "=r"(r3) : "r"(addr))
#define MMA16816F(d0, d1, d2, d3, a0, a1, a2, a3, b0, b1) \
    asm volatile("mma.sync.aligned.m16n8k16.row.col.f32.f16.f16.f32 " \
        "{%0,%1,%2,%3}, {%4,%5,%6,%7}, {%8,%9}, {%0,%1,%2,%3};" \
        : "+f"(d0), "+f"(d1), "+f"(d2), "+f"(d3) \
        : "r"(a0), "r"(a1), "r"(a2), "r"(a3), "r"(b0), "r"(b1))

__device__ __forceinline__ uint32_t sw128(uint32_t off) {
    return off ^ ((off >> 3) & 0x70);
}
__device__ __forceinline__ float fast_tanh(float x) {
    float ax = fabsf(x);
    float e  = __expf(2.0f * ax);
    float t  = 1.0f - __fdividef(2.0f, e + 1.0f);
    return copysignf(t, x);
}

// ---------------- GEMM tiling (round-10 proven config) ----------------
#define BM 128
#define BN 128
#define BKE 64                      // fp16 k per chunk (128 B rows)
#define NKC1 16                     // 16 k-chunks
#define STG_B 32768                 // per-stage bytes: A 16K + B 16K
#define SMEM_TOTAL (3 * STG_B)      // 96 KB

// ---------------- setup kernels ----------------
__global__ void convert_A_kernel(const float* __restrict__ enc) {
    size_t i = ((size_t)blockIdx.x * blockDim.x + threadIdx.x) * 8;
    float4 v0 = *(const float4*)(enc + i);
    float4 v1 = *(const float4*)(enc + i + 4);
    __half2 h[4];
    h[0] = __floats2half2_rn(v0.x, v0.y);
    h[1] = __floats2half2_rn(v0.z, v0.w);
    h[2] = __floats2half2_rn(v1.x, v1.y);
    h[3] = __floats2half2_rn(v1.z, v1.w);
    *(uint4*)(g_A1 + i) = *(uint4*)h;
}

// tiled transpose W[k][n] -> B1[n][k] (fp16), coalesced both directions.
// grid (32, 32), block 256 (= 32x8). Also zeroes scores/dU/out_context.
__global__ void convert_W_kernel(const float* __restrict__ W,
                                 float* __restrict__ out_context) {
    __shared__ float tile[32][33];
    const int tid = threadIdx.x;
    const int tx = tid & 31, ty = tid >> 5;          // 32 x 8
    const int n0 = blockIdx.x * 32, k0 = blockIdx.y * 32;
#pragma unroll
    for (int j = 0; j < 4; j++)
        tile[ty + 8 * j][tx] = W[(size_t)(k0 + ty + 8 * j) * Dd + n0 + tx];
    __syncthreads();
#pragma unroll
    for (int j = 0; j < 4; j++)
        g_B1[(size_t)(n0 + ty + 8 * j) * Dd + k0 + tx] =
            __float2half(tile[tx][ty + 8 * j]);

    int id = (blockIdx.y * 32 + blockIdx.x) * 256 + tid;   // 0..262143
    if (id < Bz * TE) g_scores[id] = 0.0f;
    if (id < Bz * Dd) { g_dU[id] = 0.0f; out_context[id] = 0.0f; }
}

// dU[b][f] = sum_k dec_last[b][k] * U[k][f]  ; grid (4, 32)
__global__ void dU_kernel(const float* __restrict__ dec, const float* __restrict__ U) {
    const int f  = blockIdx.x * 256 + threadIdx.x;
    const int k0 = blockIdx.y * 32;
    __shared__ float sdec[Bz][32];
#pragma unroll
    for (int j = 0; j < 4; j++) {
        int idx = threadIdx.x + j * 256;
        int b = idx >> 5, kk = idx & 31;
        sdec[b][kk] = dec[((size_t)b * TDd + (TDd - 1)) * Dd + k0 + kk];
    }
    __syncthreads();
    float acc[Bz];
#pragma unroll
    for (int b = 0; b < Bz; b++) acc[b] = 0.0f;
#pragma unroll
    for (int kk = 0; kk < 32; kk++) {
        float u = U[(size_t)(k0 + kk) * Dd + f];
#pragma unroll
        for (int b = 0; b < Bz; b++) acc[b] = fmaf(u, sdec[b][kk], acc[b]);
    }
#pragma unroll
    for (int b = 0; b < Bz; b++) atomicAdd(&g_dU[b * Dd + f], acc[b]);
}

// ---------------- fused GEMM + epilogue ----------------
__device__ __forceinline__ void load_chunk(uint32_t sbase, int stage, int c,
                                           int mbase, int nbase, int tid) {
    const int kb = c * BKE;
    uint32_t sA = sbase + stage * STG_B;
    uint32_t sB = sA + 16384;
#pragma unroll
    for (int i = 0; i < 4; i++) {
        int u = tid + i * 256;                 // 0..1023
        int r = u >> 3, ch = u & 7;
        uint32_t off = sw128((uint32_t)(r * 128 + ch * 16));
        cp16(sA + off, g_A1 + (size_t)(mbase + r) * Dd + kb + ch * 8);
        cp16(sB + off, g_B1 + (size_t)(nbase + r) * Dd + kb + ch * 8);
    }
    CP_COMMIT();
}

__global__ void __launch_bounds__(256, 2) gemm_score_mma(const float* __restrict__ V) {
    extern __shared__ char smem[];
    uint32_t sbase = smem_to_u32(smem);

    const int tid  = threadIdx.x;
    const int wid  = tid >> 5;
    const int lane = tid & 31;
    const int wm   = wid >> 2;      // 0..1
    const int wn   = wid & 3;       // 0..3

    const int nblk  = blockIdx.x & 7;
    const int mblk  = blockIdx.x >> 3;
    const int mbase = mblk * BM;
    const int nbase = nblk * BN;
    const int b     = mbase >> 11;

    float acc[4][4][4];
#pragma unroll
    for (int mt = 0; mt < 4; mt++)
#pragma unroll
        for (int nt = 0; nt < 4; nt++)
#pragma unroll
            for (int i = 0; i < 4; i++) acc[mt][nt][i] = 0.0f;

    const int a_r  = lane & 15;
    const int a_kc = lane >> 4;
    const int b_n  = ((lane >> 4) & 1) * 8 + (lane & 7);
    const int b_kc = (lane >> 3) & 1;

    load_chunk(sbase, 0, 0, mbase, nbase, tid);
    load_chunk(sbase, 1, 1, mbase, nbase, tid);

    int stage = 0;
    for (int c = 0; c < NKC1; c++) {
        if (c + 2 < NKC1) { CP_WAIT(1); } else { CP_WAIT(0); }
        __syncthreads();
        if (c + 2 < NKC1) {
            int ns = stage + 2; if (ns >= 3) ns -= 3;
            load_chunk(sbase, ns, c + 2, mbase, nbase, tid);
        }

        const uint32_t sA = sbase + stage * STG_B;
        const uint32_t sB = sA + 16384;
#pragma unroll
        for (int ks = 0; ks < 4; ks++) {
            uint32_t af[4][4], bf[2][4];
#pragma unroll
            for (int mt = 0; mt < 4; mt++) {
                int row = wm * 64 + mt * 16 + a_r;
                uint32_t off = sw128((uint32_t)(row * 128 + (ks * 2 + a_kc) * 16));
                LDSM_X4(af[mt][0], af[mt][1], af[mt][2], af[mt][3], sA + off);
            }
#pragma unroll
            for (int p = 0; p < 2; p++) {
                int row = wn * 32 + p * 16 + b_n;
                uint32_t off = sw128((uint32_t)(row * 128 + (ks * 2 + b_kc) * 16));
                LDSM_X4(bf[p][0], bf[p][1], bf[p][2], bf[p][3], sB + off);
            }
#pragma unroll
            for (int mt = 0; mt < 4; mt++)
#pragma unroll
                for (int nt = 0; nt < 4; nt++)
                    MMA16816F(acc[mt][nt][0], acc[mt][nt][1], acc[mt][nt][2], acc[mt][nt][3],
                              af[mt][0], af[mt][1], af[mt][2], af[mt][3],
                              bf[nt >> 1][(nt & 1) * 2], bf[nt >> 1][(nt & 1) * 2 + 1]);
        }
        stage++; if (stage >= 3) stage = 0;
    }

    // ---- fused epilogue ----
    const int q = lane >> 2;
    const int t4 = lane & 3;
#pragma unroll
    for (int mt = 0; mt < 4; mt++) {
        float s0 = 0.0f, s1 = 0.0f;
#pragma unroll
        for (int nt = 0; nt < 4; nt++) {
            int n0 = nbase + wn * 32 + nt * 8 + 2 * t4;
            float v0 = V[n0], v1 = V[n0 + 1];
            float u0 = g_dU[b * Dd + n0], u1 = g_dU[b * Dd + n0 + 1];
            s0 = fmaf(v0, fast_tanh(acc[mt][nt][0] + u0), s0);
            s0 = fmaf(v1, fast_tanh(acc[mt][nt][1] + u1), s0);
            s1 = fmaf(v0, fast_tanh(acc[mt][nt][2] + u0), s1);
            s1 = fmaf(v1, fast_tanh(acc[mt][nt][3] + u1), s1);
        }
        s0 += __shfl_xor_sync(0xFFFFFFFF, s0, 1);
        s0 += __shfl_xor_sync(0xFFFFFFFF, s0, 2);
        s1 += __shfl_xor_sync(0xFFFFFFFF, s1, 1);
        s1 += __shfl_xor_sync(0xFFFFFFFF, s1, 2);
        if (t4 == 0) {
            int row = mbase + wm * 64 + mt * 16 + q;
            atomicAdd(&g_scores[row], s0);
            atomicAdd(&g_scores[row + 8], s1);
        }
    }
}

// ---------------- softmax & context ----------------
__global__ void softmax_kernel(float* __restrict__ out_weights) {
    const int b = blockIdx.x;
    const int tid = threadIdx.x;
    __shared__ float red[256];
    float local[8];
    float mx = -INFINITY;
#pragma unroll
    for (int i = 0; i < 8; i++) {
        local[i] = g_scores[b * TE + tid + i * 256];
        mx = fmaxf(mx, local[i]);
    }
    red[tid] = mx;
    __syncthreads();
    for (int s = 128; s > 0; s >>= 1) {
        if (tid < s) red[tid] = fmaxf(red[tid], red[tid + s]);
        __syncthreads();
    }
    mx = red[0];
    __syncthreads();
    float sum = 0.0f;
#pragma unroll
    for (int i = 0; i < 8; i++) { local[i] = __expf(local[i] - mx); sum += local[i]; }
    red[tid] = sum;
    __syncthreads();
    for (int s = 128; s > 0; s >>= 1) {
        if (tid < s) red[tid] += red[tid + s];
        __syncthreads();
    }
    const float inv = 1.0f / red[0];
#pragma unroll
    for (int i = 0; i < 8; i++) {
        float w = local[i] * inv;
        g_weights[b * TE + tid + i * 256]   = w;
        out_weights[b * TE + tid + i * 256] = w;
    }
}

// split-T context: grid (32, 2, 8), block 256. Each thread: one half2 (2 e's),
// 256 t's. atomicAdd partial sums (out_context pre-zeroed in convert_W).
__global__ void context_kernel(float* __restrict__ out_context) {
    const int b  = blockIdx.x;
    const int e2 = blockIdx.y * 256 + threadIdx.x;   // half2 index, 0..511
    const int t0 = blockIdx.z * 256;

    __shared__ float sw[256];
    sw[threadIdx.x] = g_weights[b * TE + t0 + threadIdx.x];
    __syncthreads();

    const __half2* base = (const __half2*)(g_A1 + (size_t)b * TE * Dd) + e2;
    float ax = 0.0f, ay = 0.0f;
#pragma unroll 8
    for (int t = 0; t < 256; t++) {
        __half2 h = base[(size_t)(t0 + t) * (Dd / 2)];
        float2 f = __half22float2(h);
        ax = fmaf(sw[t], f.x, ax);
        ay = fmaf(sw[t], f.y, ay);
    }
    atomicAdd(&out_context[b * Dd + 2 * e2], ax);
    atomicAdd(&out_context[b * Dd + 2 * e2 + 1], ay);
}

// ---------------- launch ----------------
extern "C" void kernel_launch(void* const* d_in, const int* in_sizes, int n_in,
                              void* d_out, int out_size) {
    const float* enc = (const float*)d_in[0];
    const float* dec = (const float*)d_in[1];
    const float* W_a = (const float*)d_in[2];
    const float* U_a = (const float*)d_in[3];
    const float* V_a = (const float*)d_in[4];
    float* out = (float*)d_out;
    float* out_context = out;            // 32*1024
    float* out_weights = out + Bz * Dd;  // 32*2048

    static int smem_set = 0;
    if (!smem_set) {
        cudaFuncSetAttribute(gemm_score_mma, cudaFuncAttributeMaxDynamicSharedMemorySize, SMEM_TOTAL);
        smem_set = 1;
    }

    convert_A_kernel<<<(Mrows * (Dd / 8)) / 256, 256>>>(enc);
    {
        dim3 g(32, 32);
        convert_W_kernel<<<g, 256>>>(W_a, out_context);
    }
    {
        dim3 g(Dd / 256, 32);
        dU_kernel<<<g, 256>>>(dec, U_a);
    }
    gemm_score_mma<<<(Mrows / BM) * (Dd / BN), 256, SMEM_TOTAL>>>(V_a);
    softmax_kernel<<<Bz, 256>>>(out_weights);
    {
        dim3 g(Bz, 2, 8);
        context_kernel<<<g, 256>>>(out_context);
    }
}

// round 13
// speedup vs baseline: 1.4837x; 1.0108x over previous
#include <cuda_runtime.h>
#include <cuda_fp16.h>
#include <math.h>
#include <stdint.h>

// ---------------- problem constants ----------------
#define Bz 32
#define TE 2048
#define TDd 64
#define Dd 1024
#define Mrows (Bz * TE)      // 65536

// ---------------- scratch (device globals) ----------------
__device__ __half g_A1[(size_t)Mrows * Dd];   // fp16(enc)
__device__ __half g_B1[(size_t)Dd * Dd];      // W^T fp16 : [n][k]
__device__ float g_dU[Bz * Dd];
__device__ float g_scores[Bz * TE];
__device__ float g_weights[Bz * TE];

// ---------------- helpers ----------------
__device__ __forceinline__ uint32_t smem_to_u32(const void* p) {
    uint32_t a;
    asm("{ .reg .u64 t; cvta.to.shared.u64 t, %1; cvt.u32.u64 %0, t; }" : "=r"(a) : "l"(p));
    return a;
}
__device__ __forceinline__ void cp16(uint32_t s, const void* g) {
    asm volatile("cp.async.cg.shared.global [%0], [%1], 16;" :: "r"(s), "l"(g));
}
#define CP_COMMIT() asm volatile("cp.async.commit_group;" ::: "memory")
#define CP_WAIT(n)  asm volatile("cp.async.wait_group %0;" :: "n"(n) : "memory")
#define LDSM_X4(r0, r1, r2, r3, addr) \
    asm volatile("ldmatrix.sync.aligned.m8n8.x4.shared.b16 {%0,%1,%2,%3}, [%4];" \
        : "=r"(r0), "=r"(r1), "=r"(r2), "=r"(r3) : "r"(addr))
#define MMA16816F(d0, d1, d2, d3, a0, a1, a2, a3, b0, b1) \
    asm volatile("mma.sync.aligned.m16n8k16.row.col.f32.f16.f16.f32 " \
        "{%0,%1,%2,%3}, {%4,%5,%6,%7}, {%8,%9}, {%0,%1,%2,%3};" \
        : "+f"(d0), "+f"(d1), "+f"(d2), "+f"(d3) \
        : "r"(a0), "r"(a1), "r"(a2), "r"(a3), "r"(b0), "r"(b1))

__device__ __forceinline__ uint32_t sw128(uint32_t off) {
    return off ^ ((off >> 3) & 0x70);
}
__device__ __forceinline__ float fast_tanh(float x) {
    float ax = fabsf(x);
    float e  = __expf(2.0f * ax);
    float t  = 1.0f - __fdividef(2.0f, e + 1.0f);
    return copysignf(t, x);
}

// ---------------- GEMM tiling ----------------
#define BM 128
#define BN 128
#define BKE 64                      // fp16 k per chunk (128 B rows)
#define NKC1 16                     // 16 k-chunks
#define STG_B 32768                 // per-stage bytes: A 16K + B 16K
#define SMEM_TOTAL (3 * STG_B)      // 96 KB
#define GTHREADS 128                // 4 warps, 2x2 warp grid, 64x64 warp tile

// ---------------- setup kernels ----------------
__global__ void convert_A_kernel(const float* __restrict__ enc) {
    size_t i = ((size_t)blockIdx.x * blockDim.x + threadIdx.x) * 8;
    float4 v0 = *(const float4*)(enc + i);
    float4 v1 = *(const float4*)(enc + i + 4);
    __half2 h[4];
    h[0] = __floats2half2_rn(v0.x, v0.y);
    h[1] = __floats2half2_rn(v0.z, v0.w);
    h[2] = __floats2half2_rn(v1.x, v1.y);
    h[3] = __floats2half2_rn(v1.z, v1.w);
    *(uint4*)(g_A1 + i) = *(uint4*)h;
}

// tiled transpose W[k][n] -> B1[n][k] (fp16); also zeroes scores/dU/context
__global__ void convert_W_kernel(const float* __restrict__ W,
                                 float* __restrict__ out_context) {
    __shared__ float tile[32][33];
    const int tid = threadIdx.x;
    const int tx = tid & 31, ty = tid >> 5;          // 32 x 8
    const int n0 = blockIdx.x * 32, k0 = blockIdx.y * 32;
#pragma unroll
    for (int j = 0; j < 4; j++)
        tile[ty + 8 * j][tx] = W[(size_t)(k0 + ty + 8 * j) * Dd + n0 + tx];
    __syncthreads();
#pragma unroll
    for (int j = 0; j < 4; j++)
        g_B1[(size_t)(n0 + ty + 8 * j) * Dd + k0 + tx] =
            __float2half(tile[tx][ty + 8 * j]);

    int id = (blockIdx.y * 32 + blockIdx.x) * 256 + tid;
    if (id < Bz * TE) g_scores[id] = 0.0f;
    if (id < Bz * Dd) { g_dU[id] = 0.0f; out_context[id] = 0.0f; }
}

// dU[b][f] = sum_k dec_last[b][k] * U[k][f]  ; grid (4, 32)
__global__ void dU_kernel(const float* __restrict__ dec, const float* __restrict__ U) {
    const int f  = blockIdx.x * 256 + threadIdx.x;
    const int k0 = blockIdx.y * 32;
    __shared__ float sdec[Bz][32];
#pragma unroll
    for (int j = 0; j < 4; j++) {
        int idx = threadIdx.x + j * 256;
        int b = idx >> 5, kk = idx & 31;
        sdec[b][kk] = dec[((size_t)b * TDd + (TDd - 1)) * Dd + k0 + kk];
    }
    __syncthreads();
    float acc[Bz];
#pragma unroll
    for (int b = 0; b < Bz; b++) acc[b] = 0.0f;
#pragma unroll
    for (int kk = 0; kk < 32; kk++) {
        float u = U[(size_t)(k0 + kk) * Dd + f];
#pragma unroll
        for (int b = 0; b < Bz; b++) acc[b] = fmaf(u, sdec[b][kk], acc[b]);
    }
#pragma unroll
    for (int b = 0; b < Bz; b++) atomicAdd(&g_dU[b * Dd + f], acc[b]);
}

// ---------------- fused GEMM + epilogue ----------------
__device__ __forceinline__ void load_chunk(uint32_t sbase, int stage, int c,
                                           int mbase, int nbase, int tid) {
    const int kb = c * BKE;
    uint32_t sA = sbase + stage * STG_B;
    uint32_t sB = sA + 16384;
#pragma unroll
    for (int i = 0; i < 8; i++) {
        int u = tid + i * GTHREADS;            // 0..1023
        int r = u >> 3, ch = u & 7;
        uint32_t off = sw128((uint32_t)(r * 128 + ch * 16));
        cp16(sA + off, g_A1 + (size_t)(mbase + r) * Dd + kb + ch * 8);
        cp16(sB + off, g_B1 + (size_t)(nbase + r) * Dd + kb + ch * 8);
    }
    CP_COMMIT();
}

__global__ void __launch_bounds__(GTHREADS, 2) gemm_score_mma(const float* __restrict__ V) {
    extern __shared__ char smem[];
    uint32_t sbase = smem_to_u32(smem);

    const int tid  = threadIdx.x;
    const int wid  = tid >> 5;      // 0..3
    const int lane = tid & 31;
    const int wm   = wid >> 1;      // 0..1 : 64 rows
    const int wn   = wid & 1;       // 0..1 : 64 cols

    const int nblk  = blockIdx.x & 7;
    const int mblk  = blockIdx.x >> 3;
    const int mbase = mblk * BM;
    const int nbase = nblk * BN;
    const int b     = mbase >> 11;

    float acc[4][8][4];
#pragma unroll
    for (int mt = 0; mt < 4; mt++)
#pragma unroll
        for (int nt = 0; nt < 8; nt++)
#pragma unroll
            for (int i = 0; i < 4; i++) acc[mt][nt][i] = 0.0f;

    const int a_r  = lane & 15;
    const int a_kc = lane >> 4;
    const int b_n  = ((lane >> 4) & 1) * 8 + (lane & 7);
    const int b_kc = (lane >> 3) & 1;

    load_chunk(sbase, 0, 0, mbase, nbase, tid);
    load_chunk(sbase, 1, 1, mbase, nbase, tid);

    int stage = 0;
    for (int c = 0; c < NKC1; c++) {
        if (c + 2 < NKC1) { CP_WAIT(1); } else { CP_WAIT(0); }
        __syncthreads();
        if (c + 2 < NKC1) {
            int ns = stage + 2; if (ns >= 3) ns -= 3;
            load_chunk(sbase, ns, c + 2, mbase, nbase, tid);
        }

        const uint32_t sA = sbase + stage * STG_B;
        const uint32_t sB = sA + 16384;
#pragma unroll
        for (int ks = 0; ks < 4; ks++) {
            uint32_t af[4][4], bf[4][4];
#pragma unroll
            for (int mt = 0; mt < 4; mt++) {
                int row = wm * 64 + mt * 16 + a_r;
                uint32_t off = sw128((uint32_t)(row * 128 + (ks * 2 + a_kc) * 16));
                LDSM_X4(af[mt][0], af[mt][1], af[mt][2], af[mt][3], sA + off);
            }
#pragma unroll
            for (int p = 0; p < 4; p++) {
                int row = wn * 64 + p * 16 + b_n;
                uint32_t off = sw128((uint32_t)(row * 128 + (ks * 2 + b_kc) * 16));
                LDSM_X4(bf[p][0], bf[p][1], bf[p][2], bf[p][3], sB + off);
            }
#pragma unroll
            for (int mt = 0; mt < 4; mt++)
#pragma unroll
                for (int nt = 0; nt < 8; nt++)
                    MMA16816F(acc[mt][nt][0], acc[mt][nt][1], acc[mt][nt][2], acc[mt][nt][3],
                              af[mt][0], af[mt][1], af[mt][2], af[mt][3],
                              bf[nt >> 1][(nt & 1) * 2], bf[nt >> 1][(nt & 1) * 2 + 1]);
        }
        stage++; if (stage >= 3) stage = 0;
    }

    // ---- fused epilogue: scores[m] += sum_n V[n]*tanh(C[m][n] + dU[b][n]) ----
    const int q = lane >> 2;
    const int t4 = lane & 3;
#pragma unroll
    for (int mt = 0; mt < 4; mt++) {
        float s0 = 0.0f, s1 = 0.0f;
#pragma unroll
        for (int nt = 0; nt < 8; nt++) {
            int n0 = nbase + wn * 64 + nt * 8 + 2 * t4;
            float v0 = V[n0], v1 = V[n0 + 1];
            float u0 = g_dU[b * Dd + n0], u1 = g_dU[b * Dd + n0 + 1];
            s0 = fmaf(v0, fast_tanh(acc[mt][nt][0] + u0), s0);
            s0 = fmaf(v1, fast_tanh(acc[mt][nt][1] + u1), s0);
            s1 = fmaf(v0, fast_tanh(acc[mt][nt][2] + u0), s1);
            s1 = fmaf(v1, fast_tanh(acc[mt][nt][3] + u1), s1);
        }
        s0 += __shfl_xor_sync(0xFFFFFFFF, s0, 1);
        s0 += __shfl_xor_sync(0xFFFFFFFF, s0, 2);
        s1 += __shfl_xor_sync(0xFFFFFFFF, s1, 1);
        s1 += __shfl_xor_sync(0xFFFFFFFF, s1, 2);
        if (t4 == 0) {
            int row = mbase + wm * 64 + mt * 16 + q;
            atomicAdd(&g_scores[row], s0);
            atomicAdd(&g_scores[row + 8], s1);
        }
    }
}

// ---------------- softmax & context ----------------
__global__ void softmax_kernel(float* __restrict__ out_weights) {
    const int b = blockIdx.x;
    const int tid = threadIdx.x;
    __shared__ float red[256];
    float local[8];
    float mx = -INFINITY;
#pragma unroll
    for (int i = 0; i < 8; i++) {
        local[i] = g_scores[b * TE + tid + i * 256];
        mx = fmaxf(mx, local[i]);
    }
    red[tid] = mx;
    __syncthreads();
    for (int s = 128; s > 0; s >>= 1) {
        if (tid < s) red[tid] = fmaxf(red[tid], red[tid + s]);
        __syncthreads();
    }
    mx = red[0];
    __syncthreads();
    float sum = 0.0f;
#pragma unroll
    for (int i = 0; i < 8; i++) { local[i] = __expf(local[i] - mx); sum += local[i]; }
    red[tid] = sum;
    __syncthreads();
    for (int s = 128; s > 0; s >>= 1) {
        if (tid < s) red[tid] += red[tid + s];
        __syncthreads();
    }
    const float inv = 1.0f / red[0];
#pragma unroll
    for (int i = 0; i < 8; i++) {
        float w = local[i] * inv;
        g_weights[b * TE + tid + i * 256]   = w;
        out_weights[b * TE + tid + i * 256] = w;
    }
}

// split-T context: grid (32, 2, 8), block 256
__global__ void context_kernel(float* __restrict__ out_context) {
    const int b  = blockIdx.x;
    const int e2 = blockIdx.y * 256 + threadIdx.x;   // half2 index
    const int t0 = blockIdx.z * 256;

    __shared__ float sw[256];
    sw[threadIdx.x] = g_weights[b * TE + t0 + threadIdx.x];
    __syncthreads();

    const __half2* base = (const __half2*)(g_A1 + (size_t)b * TE * Dd) + e2;
    float ax = 0.0f, ay = 0.0f;
#pragma unroll 8
    for (int t = 0; t < 256; t++) {
        __half2 h = base[(size_t)(t0 + t) * (Dd / 2)];
        float2 f = __half22float2(h);
        ax = fmaf(sw[t], f.x, ax);
        ay = fmaf(sw[t], f.y, ay);
    }
    atomicAdd(&out_context[b * Dd + 2 * e2], ax);
    atomicAdd(&out_context[b * Dd + 2 * e2 + 1], ay);
}

// ---------------- launch ----------------
extern "C" void kernel_launch(void* const* d_in, const int* in_sizes, int n_in,
                              void* d_out, int out_size) {
    const float* enc = (const float*)d_in[0];
    const float* dec = (const float*)d_in[1];
    const float* W_a = (const float*)d_in[2];
    const float* U_a = (const float*)d_in[3];
    const float* V_a = (const float*)d_in[4];
    float* out = (float*)d_out;
    float* out_context = out;            // 32*1024
    float* out_weights = out + Bz * Dd;  // 32*2048

    static int smem_set = 0;
    if (!smem_set) {
        cudaFuncSetAttribute(gemm_score_mma, cudaFuncAttributeMaxDynamicSharedMemorySize, SMEM_TOTAL);
        smem_set = 1;
    }

    convert_A_kernel<<<(Mrows * (Dd / 8)) / 256, 256>>>(enc);
    {
        dim3 g(32, 32);
        convert_W_kernel<<<g, 256>>>(W_a, out_context);
    }
    {
        dim3 g(Dd / 256, 32);
        dU_kernel<<<g, 256>>>(dec, U_a);
    }
    gemm_score_mma<<<(Mrows / BM) * (Dd / BN), GTHREADS, SMEM_TOTAL>>>(V_a);
    softmax_kernel<<<Bz, 256>>>(out_weights);
    {
        dim3 g(Bz, 2, 8);
        context_kernel<<<g, 256>>>(out_context);
    }
}